// round 16
// baseline (speedup 1.0000x reference)
#include <cuda_runtime.h>
#include <cstdint>
#include <cstddef>

#define CC 256
#define BN 64
#define LL 4096
#define BB 64
#define EE 4
#define TL 32
#define NT 256
#define XS_STRIDE 40
#define S3P 5120
#define H1_OFF 10240
#define H2_OFF 12800
#define WS_OFF 15360
#define SMEM_FLOATS 25600
#define SMEM_BYTES (SMEM_FLOATS * 4)

// pre-truncated weight mirror: w1 | wp | w3 | w2(reordered [e][d][m][k])
#define W1T 0
#define WPT 65536
#define W3T 327680
#define W2T 393216
#define WT_TOTAL 442368
__device__ float g_wt[WT_TOTAL];

__device__ float g_gatex[BB * CC];
__device__ float g_gates[BB * EE];

__device__ __forceinline__ unsigned cvt_tf32(float f) {
    unsigned u; asm("cvt.rna.tf32.f32 %0, %1;" : "=r"(u) : "f"(f)); return u;
}
__device__ __forceinline__ float tf32f(float f) {
    return __uint_as_float(cvt_tf32(f));
}
__device__ __forceinline__ void mma_tf32(float* c, const unsigned* a, const unsigned* b) {
    asm("mma.sync.aligned.m16n8k8.row.col.f32.tf32.tf32.f32 "
        "{%0,%1,%2,%3},{%4,%5,%6,%7},{%8,%9},{%0,%1,%2,%3};"
        : "+f"(c[0]), "+f"(c[1]), "+f"(c[2]), "+f"(c[3])
        : "r"(a[0]), "r"(a[1]), "r"(a[2]), "r"(a[3]), "r"(b[0]), "r"(b[1]));
}
__device__ __forceinline__ void cpa16(float* dst, const float* src) {
    unsigned s = (unsigned)__cvta_generic_to_shared(dst);
    asm volatile("cp.async.ca.shared.global [%0], [%1], 16;" :: "r"(s), "l"(src));
}
#define CP_COMMIT() asm volatile("cp.async.commit_group;")
#define CP_WAIT0()  asm volatile("cp.async.wait_group 0;" ::: "memory")

// ---------------- kernel 0: truncate + reorder weights into g_wt ----------------
__global__ void prep_kernel(const float* __restrict__ w1, const float* __restrict__ w2,
                            const float* __restrict__ w3, const float* __restrict__ wp) {
    int i = blockIdx.x * 256 + threadIdx.x;
    if (i >= WT_TOTAL) return;
    if (i < WPT)        g_wt[i] = tf32f(w1[i]);
    else if (i < W3T)   g_wt[i] = tf32f(wp[i - WPT]);
    else if (i < W2T)   g_wt[i] = tf32f(w3[i - W3T]);
    else {
        int j = i - W2T;
        int k = j & 63, m = (j >> 6) & 63, de = j >> 12;
        int d = de % 3, e = de / 3;
        g_wt[i] = tf32f(w2[(size_t)(e * BN + m) * 192 + k * 3 + d]);
    }
}

// ---------------- kernel 1: gate_x = mean_l x ----------------
__global__ void mean_kernel(const float* __restrict__ x) {
    int row = blockIdx.x;
    const float4* xr = (const float4*)(x + (size_t)row * LL);
    float s = 0.f;
    for (int i = threadIdx.x; i < LL / 4; i += 256) {
        float4 v = xr[i];
        s += (v.x + v.y) + (v.z + v.w);
    }
#pragma unroll
    for (int o = 16; o; o >>= 1) s += __shfl_xor_sync(0xffffffffu, s, o);
    __shared__ float ps[8];
    if ((threadIdx.x & 31) == 0) ps[threadIdx.x >> 5] = s;
    __syncthreads();
    if (threadIdx.x == 0) {
        float t = 0.f;
#pragma unroll
        for (int i = 0; i < 8; i++) t += ps[i];
        g_gatex[row] = t * (1.0f / LL);
    }
}

// ---------------- kernel 2: gating + loss (1 block, 64 thr) ----------------
__global__ void gating_kernel(const float* __restrict__ noise,
                              const float* __restrict__ wg,
                              const float* __restrict__ wn,
                              float* __restrict__ loss_out) {
    __shared__ float sh_g[BB][EE], sh_p[BB][EE];
    int b = threadIdx.x;
    float clean[4] = {0,0,0,0}, rawn[4] = {0,0,0,0};
    for (int c = 0; c < CC; c++) {
        float v = g_gatex[b * CC + c];
#pragma unroll
        for (int e = 0; e < 4; e++) {
            clean[e] = fmaf(v, wg[c * 4 + e], clean[e]);
            rawn[e]  = fmaf(v, wn[c * 4 + e], rawn[e]);
        }
    }
    float sd[4], noisy[4];
#pragma unroll
    for (int e = 0; e < 4; e++) {
        float r = rawn[e];
        float sp = (r > 20.f) ? r : log1pf(expf(r));
        sd[e] = sp + 0.01f;
        noisy[e] = clean[e] + noise[b * 4 + e] * sd[e];
    }
    float mx = fmaxf(fmaxf(noisy[0], noisy[1]), fmaxf(noisy[2], noisy[3]));
    float sm[4], ssum = 0.f;
#pragma unroll
    for (int e = 0; e < 4; e++) { sm[e] = expf(noisy[e] - mx); ssum += sm[e]; }
#pragma unroll
    for (int e = 0; e < 4; e++) sm[e] /= ssum;
    int idx[4] = {0,1,2,3};
#pragma unroll
    for (int i = 0; i < 3; i++)
#pragma unroll
        for (int j = 0; j < 3; j++)
            if (j < 3 - i && sm[idx[j+1]] > sm[idx[j]]) { int t = idx[j]; idx[j] = idx[j+1]; idx[j+1] = t; }
    float v1 = sm[idx[1]], v2 = sm[idx[2]];
    float eb = expf(v1 - sm[idx[0]]);
    float g0 = 1.f / (1.f + eb), g1 = eb / (1.f + eb);
    float gr[4] = {0,0,0,0};
    gr[idx[0]] = g0; gr[idx[1]] = g1;
#pragma unroll
    for (int e = 0; e < 4; e++) { g_gates[b * 4 + e] = gr[e]; sh_g[b][e] = gr[e]; }
#pragma unroll
    for (int e = 0; e < 4; e++) {
        bool isin = noisy[e] > v2;
        float thr = isin ? v2 : v1;
        sh_p[b][e] = normcdff((clean[e] - thr) / sd[e]);
    }
    __syncthreads();
    if (b == 0) {
        float imp[4] = {0,0,0,0}, ld[4] = {0,0,0,0};
        for (int bb = 0; bb < BB; bb++)
#pragma unroll
            for (int e = 0; e < 4; e++) { imp[e] += sh_g[bb][e]; ld[e] += sh_p[bb][e]; }
        float m1 = (imp[0]+imp[1]+imp[2]+imp[3]) * 0.25f, va = 0.f;
#pragma unroll
        for (int e = 0; e < 4; e++) { float d = imp[e]-m1; va += d*d; }
        float cv1 = (va * (1.f/3.f)) / (m1*m1 + 1e-10f);
        float m2 = (ld[0]+ld[1]+ld[2]+ld[3]) * 0.25f, vb = 0.f;
#pragma unroll
        for (int e = 0; e < 4; e++) { float d = ld[e]-m2; vb += d*d; }
        float cv2 = (vb * (1.f/3.f)) / (m2*m2 + 1e-10f);
        loss_out[0] = 0.01f * (cv1 + cv2);
    }
}

// ---------------- kernel 3: fused experts (TF32 mma, TL=32, 2 blocks/SM) ----------------
__global__ void __launch_bounds__(NT, 2)
expert_kernel(const float* __restrict__ x, const float* __restrict__ b1,
              const float* __restrict__ b2, const float* __restrict__ b3,
              const float* __restrict__ bp, float* __restrict__ y) {
    extern __shared__ float smf[];
    float* xs = smf;
    float* h1 = smf + H1_OFF;
    float* h2 = smf + H2_OFF;
    float* ws = smf + WS_OFF;
    const int tid = threadIdx.x;
    const int b = blockIdx.y;
    const int l0 = blockIdx.x * TL;
    const int w = tid >> 5, lane = tid & 31;
    const int gid = lane >> 2, tig = lane & 3;

    // load x tile (32 cols) + halo, pre-truncated to TF32
    {
        const float* xb = x + (size_t)b * CC * LL + l0;
        for (int i = tid; i < CC * 8; i += NT) {
            int c = i >> 3, j = i & 7;
            float4 v = *(const float4*)(xb + (size_t)c * LL + j * 4);
            v.x = tf32f(v.x); v.y = tf32f(v.y); v.z = tf32f(v.z); v.w = tf32f(v.w);
            *(float4*)&xs[c * XS_STRIDE + 4 + j * 4] = v;
        }
        for (int i = tid; i < 2 * CC; i += NT) {
            int side = i >> 8, c = i & 255;
            int l = side ? (l0 + TL) : (l0 - 1);
            float v = 0.f;
            if (l >= 0 && l < LL) v = tf32f(xb[(size_t)c * LL + (side ? TL : -1)]);
            xs[c * XS_STRIDE + (side ? (TL + 4) : 3)] = v;
        }
    }
    __syncthreads();

    bool wrote = false;
    for (int e = 0; e < EE; e++) {
        float gv = g_gates[b * 4 + e];
        if (gv == 0.f) continue;

        // ---- stage 1: h1 = relu(W1@x + b1), M=64 N=32 K=256, weights [m][68] cp.async ----
        {
            const int m0w = (w & 3) * 16;
            const int nbase = (w >> 2) * 16;
            const int r0 = m0w + gid;
            float cf[2][4];
            float bias0 = b1[e*BN + r0], bias1 = b1[e*BN + r0 + 8];
#pragma unroll
            for (int nt = 0; nt < 2; nt++) {
                cf[nt][0] = bias0; cf[nt][1] = bias0;
                cf[nt][2] = bias1; cf[nt][3] = bias1;
            }
            const int hside = tid >> 6, hm = tid & 63;
            const int hp = (hside | (tid >> 7)) ? (TL + 4) : 3;
            const int hl = hside ? (l0 + TL) : (l0 - 1);
            const bool hvalid = (tid < 128) && (hl >= 0) && (hl < LL);
            float hacc = (tid < 128) ? b1[e * BN + hm] : 0.f;
            const float* w1t = g_wt + W1T + (size_t)e * BN * CC;
#pragma unroll
            for (int t = 0; t < 4; t++) {
                int i = tid + t * NT, kg = i & 15, m = i >> 4;
                cpa16(&ws[m*68 + kg*4], w1t + m*CC + kg*4);
            }
            CP_COMMIT(); CP_WAIT0();
            __syncthreads();
            for (int c = 0; c < 4; c++) {
                if (c < 3) {
                    float* nb = ws + ((c+1) & 1) * S3P;
#pragma unroll
                    for (int t = 0; t < 4; t++) {
                        int i = tid + t * NT, kg = i & 15, m = i >> 4;
                        cpa16(&nb[m*68 + kg*4], w1t + m*CC + (c+1)*64 + kg*4);
                    }
                    CP_COMMIT();
                }
                const float* wb = ws + (c & 1) * S3P;
                const float* rA0 = wb + r0 * 68;
                const float* rA1 = wb + (r0 + 8) * 68;
#pragma unroll
                for (int ks = 0; ks < 8; ks++) {
                    unsigned af[4];
                    af[0] = __float_as_uint(rA0[8*ks + tig]);
                    af[1] = __float_as_uint(rA1[8*ks + tig]);
                    af[2] = __float_as_uint(rA0[8*ks + tig + 4]);
                    af[3] = __float_as_uint(rA1[8*ks + tig + 4]);
                    const float* rB0 = &xs[(c*64 + 8*ks + tig) * XS_STRIDE + 4 + nbase];
                    const float* rB1 = rB0 + 4 * XS_STRIDE;
#pragma unroll
                    for (int nt = 0; nt < 2; nt++) {
                        unsigned bf[2] = {__float_as_uint(rB0[nt*8 + gid]),
                                          __float_as_uint(rB1[nt*8 + gid])};
                        mma_tf32(cf[nt], af, bf);
                    }
                }
                if (tid < 128) {
                    const float* hrow = wb + hm * 68;
#pragma unroll 4
                    for (int k4 = 0; k4 < 16; k4++) {
                        float4 wv = *(const float4*)&hrow[k4*4];
                        const float* xp = &xs[(c*64 + k4*4)*XS_STRIDE + hp];
                        hacc = fmaf(wv.x, xp[0], hacc);
                        hacc = fmaf(wv.y, xp[XS_STRIDE], hacc);
                        hacc = fmaf(wv.z, xp[2*XS_STRIDE], hacc);
                        hacc = fmaf(wv.w, xp[3*XS_STRIDE], hacc);
                    }
                }
                CP_WAIT0();
                __syncthreads();
            }
#pragma unroll
            for (int nt = 0; nt < 2; nt++) {
                int col = 4 + nbase + nt*8 + 2*tig;
                float2 v0 = {tf32f(fmaxf(cf[nt][0],0.f)), tf32f(fmaxf(cf[nt][1],0.f))};
                float2 v1 = {tf32f(fmaxf(cf[nt][2],0.f)), tf32f(fmaxf(cf[nt][3],0.f))};
                *(float2*)&h1[r0*XS_STRIDE + col] = v0;
                *(float2*)&h1[(r0+8)*XS_STRIDE + col] = v1;
            }
            if (tid < 128) h1[hm * XS_STRIDE + hp] = hvalid ? tf32f(fmaxf(hacc, 0.f)) : 0.f;
        }

        // ---- stage 2: h2 = relu(conv3(h1) + b2), taps double-buffered ----
        {
            const int m0w = (w & 3) * 16;
            const int nbase = (w >> 2) * 16;
            const int r0 = m0w + gid;
            const float* w2t = g_wt + W2T + (size_t)e * 3 * BN * 64;
            // prologue: cp tap 0
#pragma unroll
            for (int t = 0; t < 4; t++) {
                int i = tid + t * NT, kg = i & 15, m = i >> 4;
                cpa16(&ws[m*68 + kg*4], w2t + m*64 + kg*4);
            }
            CP_COMMIT();
            float cf[2][4];
            float bias0 = b2[e*BN + r0], bias1 = b2[e*BN + r0 + 8];
#pragma unroll
            for (int nt = 0; nt < 2; nt++) {
                cf[nt][0] = bias0; cf[nt][1] = bias0;
                cf[nt][2] = bias1; cf[nt][3] = bias1;
            }
            CP_WAIT0();
            __syncthreads();   // tap0 ready + h1 visible
#pragma unroll
            for (int d = 0; d < 3; d++) {
                if (d < 2) {
                    float* nb = ws + ((d+1) & 1) * S3P;
#pragma unroll
                    for (int t = 0; t < 4; t++) {
                        int i = tid + t * NT, kg = i & 15, m = i >> 4;
                        cpa16(&nb[m*68 + kg*4], w2t + ((d+1)*BN + m)*64 + kg*4);
                    }
                    CP_COMMIT();
                }
                const float* wd = ws + (d & 1) * S3P;
                const float* rA0 = wd + r0 * 68;
                const float* rA1 = wd + (r0 + 8) * 68;
#pragma unroll
                for (int ks = 0; ks < 8; ks++) {
                    unsigned af[4];
                    af[0] = __float_as_uint(rA0[8*ks + tig]);
                    af[1] = __float_as_uint(rA1[8*ks + tig]);
                    af[2] = __float_as_uint(rA0[8*ks + tig + 4]);
                    af[3] = __float_as_uint(rA1[8*ks + tig + 4]);
                    const float* rB0 = &h1[(8*ks + tig) * XS_STRIDE + 3 + d + nbase];
                    const float* rB1 = rB0 + 4 * XS_STRIDE;
#pragma unroll
                    for (int nt = 0; nt < 2; nt++) {
                        unsigned bf[2] = {__float_as_uint(rB0[nt*8 + gid]),
                                          __float_as_uint(rB1[nt*8 + gid])};
                        mma_tf32(cf[nt], af, bf);
                    }
                }
                CP_WAIT0();
                __syncthreads();
            }
#pragma unroll
            for (int nt = 0; nt < 2; nt++) {
                int col = 4 + nbase + nt*8 + 2*tig;
                float2 v0 = {tf32f(fmaxf(cf[nt][0],0.f)), tf32f(fmaxf(cf[nt][1],0.f))};
                float2 v1 = {tf32f(fmaxf(cf[nt][2],0.f)), tf32f(fmaxf(cf[nt][3],0.f))};
                *(float2*)&h2[r0*XS_STRIDE + col] = v0;
                *(float2*)&h2[(r0+8)*XS_STRIDE + col] = v1;
            }
        }

        // ---- stage 3: y += g*relu(Wp@x + W3@h2 + bp + b3), k-chunks of 16, [m][20] ----
        {
            const int m0w = w * 32;
            const float* wpt = g_wt + WPT + (size_t)e * CC * CC;
            const float* w3t = g_wt + W3T + (size_t)e * CC * BN;
            float cf[2][4][4];
#pragma unroll
            for (int mt = 0; mt < 2; mt++) {
                int r0 = m0w + 16*mt + gid;
                float bias0 = bp[e*CC + r0] + b3[e*CC + r0];
                float bias1 = bp[e*CC + r0 + 8] + b3[e*CC + r0 + 8];
#pragma unroll
                for (int nt = 0; nt < 4; nt++) {
                    cf[mt][nt][0] = bias0; cf[mt][nt][1] = bias0;
                    cf[mt][nt][2] = bias1; cf[mt][nt][3] = bias1;
                }
            }
            // prologue: cp chunk 0 (wp k=0..15)
#pragma unroll
            for (int t = 0; t < 4; t++) {
                int i = tid + t * NT, kg = i & 3, m = i >> 2;
                cpa16(&ws[m*20 + kg*4], wpt + m*CC + kg*4);
            }
            CP_COMMIT(); CP_WAIT0();
            __syncthreads();   // chunk0 ready + h2 visible
            for (int ch = 0; ch < 20; ch++) {
                if (ch < 19) {
                    int nc = ch + 1;
                    float* nb = ws + (nc & 1) * S3P;
#pragma unroll
                    for (int t = 0; t < 4; t++) {
                        int i = tid + t * NT, kg = i & 3, m = i >> 2;
                        const float* src = (nc < 16) ? (wpt + m*CC + nc*16 + kg*4)
                                                     : (w3t + m*BN + (nc-16)*16 + kg*4);
                        cpa16(&nb[m*20 + kg*4], src);
                    }
                    CP_COMMIT();
                }
                const float* wb = ws + (ch & 1) * S3P;
                const float* opb = (ch < 16) ? &xs[(ch*16)*XS_STRIDE + 4]
                                             : &h2[((ch-16)*16)*XS_STRIDE + 4];
#pragma unroll
                for (int ks = 0; ks < 2; ks++) {
                    unsigned af[2][4];
#pragma unroll
                    for (int mt = 0; mt < 2; mt++) {
                        const float* rA0 = wb + (m0w + 16*mt + gid) * 20;
                        const float* rA1 = rA0 + 8 * 20;
                        af[mt][0] = __float_as_uint(rA0[8*ks + tig]);
                        af[mt][1] = __float_as_uint(rA1[8*ks + tig]);
                        af[mt][2] = __float_as_uint(rA0[8*ks + tig + 4]);
                        af[mt][3] = __float_as_uint(rA1[8*ks + tig + 4]);
                    }
                    const float* rowB0 = opb + (8*ks + tig) * XS_STRIDE;
                    const float* rowB1 = opb + (8*ks + tig + 4) * XS_STRIDE;
                    unsigned bf[4][2];
#pragma unroll
                    for (int nt = 0; nt < 4; nt++) {
                        bf[nt][0] = __float_as_uint(rowB0[nt*8 + gid]);
                        bf[nt][1] = __float_as_uint(rowB1[nt*8 + gid]);
                    }
#pragma unroll
                    for (int mt = 0; mt < 2; mt++)
#pragma unroll
                        for (int nt = 0; nt < 4; nt++)
                            mma_tf32(cf[mt][nt], af[mt], bf[nt]);
                }
                CP_WAIT0();
                __syncthreads();
            }
#pragma unroll
            for (int mt = 0; mt < 2; mt++) {
                int r0 = m0w + 16*mt + gid;
#pragma unroll
                for (int nt = 0; nt < 4; nt++) {
                    float* yp0 = y + ((size_t)b*CC + r0)*LL + l0 + nt*8 + 2*tig;
                    float* yp1 = yp0 + (size_t)8*LL;
                    float2 v0 = {fmaxf(cf[mt][nt][0],0.f)*gv, fmaxf(cf[mt][nt][1],0.f)*gv};
                    float2 v1 = {fmaxf(cf[mt][nt][2],0.f)*gv, fmaxf(cf[mt][nt][3],0.f)*gv};
                    if (wrote) {
                        float2 o0 = *(float2*)yp0, o1 = *(float2*)yp1;
                        v0.x += o0.x; v0.y += o0.y; v1.x += o1.x; v1.y += o1.y;
                    }
                    *(float2*)yp0 = v0; *(float2*)yp1 = v1;
                }
            }
        }
        wrote = true;
    }
}

extern "C" void kernel_launch(void* const* d_in, const int* in_sizes, int n_in,
                              void* d_out, int out_size) {
    const float* x     = (const float*)d_in[0];
    const float* noise = (const float*)d_in[1];
    const float* wg    = (const float*)d_in[2];
    const float* wn    = (const float*)d_in[3];
    const float* W1    = (const float*)d_in[4];
    const float* b1    = (const float*)d_in[5];
    const float* W2    = (const float*)d_in[6];
    const float* b2    = (const float*)d_in[7];
    const float* W3    = (const float*)d_in[8];
    const float* b3    = (const float*)d_in[9];
    const float* Wp    = (const float*)d_in[10];
    const float* bp    = (const float*)d_in[11];
    float* y = (float*)d_out;
    float* loss = y + (size_t)out_size - 1;

    cudaFuncSetAttribute(expert_kernel, cudaFuncAttributeMaxDynamicSharedMemorySize, SMEM_BYTES);

    prep_kernel<<<(WT_TOTAL + 255) / 256, 256>>>(W1, W2, W3, Wp);  // also keeps ncu window
    mean_kernel<<<BB * CC, 256>>>(x);
    gating_kernel<<<1, BB>>>(noise, wg, wn, loss);
    dim3 grid(LL / TL, BB);
    expert_kernel<<<grid, NT, SMEM_BYTES>>>(x, b1, b2, b3, bp, y);
}

// round 17
// speedup vs baseline: 1.2357x; 1.2357x over previous
#include <cuda_runtime.h>
#include <cstdint>
#include <cstddef>

#define CC 256
#define BN 64
#define LL 4096
#define BB 64
#define EE 4
#define TL 64
#define NT 512
#define XS_STRIDE 72
#define S1P 4352
#define S3P 9216
#define H1_OFF (CC * XS_STRIDE)
#define H2_OFF (H1_OFF + BN * XS_STRIDE)
#define WS_OFF (H2_OFF + BN * XS_STRIDE)
#define SMEM_FLOATS (WS_OFF + 2 * S3P)
#define SMEM_BYTES (SMEM_FLOATS * 4)

// pre-truncated weight mirror: w1 | wp | w3 | w2(reordered [e][d][m][k])
#define W1T 0
#define WPT 65536
#define W3T 327680
#define W2T 393216
#define WT_TOTAL 442368
__device__ float g_wt[WT_TOTAL];

__device__ float g_gatex[BB * CC];
__device__ float g_gates[BB * EE];

__device__ __forceinline__ unsigned cvt_tf32(float f) {
    unsigned u; asm("cvt.rna.tf32.f32 %0, %1;" : "=r"(u) : "f"(f)); return u;
}
__device__ __forceinline__ float tf32f(float f) {
    return __uint_as_float(cvt_tf32(f));
}
__device__ __forceinline__ void mma_tf32(float* c, const unsigned* a, const unsigned* b) {
    asm("mma.sync.aligned.m16n8k8.row.col.f32.tf32.tf32.f32 "
        "{%0,%1,%2,%3},{%4,%5,%6,%7},{%8,%9},{%0,%1,%2,%3};"
        : "+f"(c[0]), "+f"(c[1]), "+f"(c[2]), "+f"(c[3])
        : "r"(a[0]), "r"(a[1]), "r"(a[2]), "r"(a[3]), "r"(b[0]), "r"(b[1]));
}
__device__ __forceinline__ void cpa16(float* dst, const float* src) {
    unsigned s = (unsigned)__cvta_generic_to_shared(dst);
    asm volatile("cp.async.ca.shared.global [%0], [%1], 16;" :: "r"(s), "l"(src));
}
#define CP_COMMIT() asm volatile("cp.async.commit_group;")
#define CP_WAIT0()  asm volatile("cp.async.wait_group 0;" ::: "memory")

// ---------------- kernel 0: truncate + reorder weights into g_wt ----------------
__global__ void prep_kernel(const float* __restrict__ w1, const float* __restrict__ w2,
                            const float* __restrict__ w3, const float* __restrict__ wp) {
    int i = blockIdx.x * 256 + threadIdx.x;
    if (i >= WT_TOTAL) return;
    if (i < WPT)        g_wt[i] = tf32f(w1[i]);
    else if (i < W3T)   g_wt[i] = tf32f(wp[i - WPT]);
    else if (i < W2T)   g_wt[i] = tf32f(w3[i - W3T]);
    else {
        int j = i - W2T;
        int k = j & 63, m = (j >> 6) & 63, de = j >> 12;
        int d = de % 3, e = de / 3;
        g_wt[i] = tf32f(w2[(size_t)(e * BN + m) * 192 + k * 3 + d]);
    }
}

// ---------------- kernel 1: gate_x = mean_l x ----------------
__global__ void mean_kernel(const float* __restrict__ x) {
    int row = blockIdx.x;
    const float4* xr = (const float4*)(x + (size_t)row * LL);
    float s = 0.f;
    for (int i = threadIdx.x; i < LL / 4; i += 256) {
        float4 v = xr[i];
        s += (v.x + v.y) + (v.z + v.w);
    }
#pragma unroll
    for (int o = 16; o; o >>= 1) s += __shfl_xor_sync(0xffffffffu, s, o);
    __shared__ float ps[8];
    if ((threadIdx.x & 31) == 0) ps[threadIdx.x >> 5] = s;
    __syncthreads();
    if (threadIdx.x == 0) {
        float t = 0.f;
#pragma unroll
        for (int i = 0; i < 8; i++) t += ps[i];
        g_gatex[row] = t * (1.0f / LL);
    }
}

// ---------------- kernel 2: gating + loss (1 block, 64 thr) ----------------
__global__ void gating_kernel(const float* __restrict__ noise,
                              const float* __restrict__ wg,
                              const float* __restrict__ wn,
                              float* __restrict__ loss_out) {
    __shared__ float sh_g[BB][EE], sh_p[BB][EE];
    int b = threadIdx.x;
    float clean[4] = {0,0,0,0}, rawn[4] = {0,0,0,0};
    for (int c = 0; c < CC; c++) {
        float v = g_gatex[b * CC + c];
#pragma unroll
        for (int e = 0; e < 4; e++) {
            clean[e] = fmaf(v, wg[c * 4 + e], clean[e]);
            rawn[e]  = fmaf(v, wn[c * 4 + e], rawn[e]);
        }
    }
    float sd[4], noisy[4];
#pragma unroll
    for (int e = 0; e < 4; e++) {
        float r = rawn[e];
        float sp = (r > 20.f) ? r : log1pf(expf(r));
        sd[e] = sp + 0.01f;
        noisy[e] = clean[e] + noise[b * 4 + e] * sd[e];
    }
    float mx = fmaxf(fmaxf(noisy[0], noisy[1]), fmaxf(noisy[2], noisy[3]));
    float sm[4], ssum = 0.f;
#pragma unroll
    for (int e = 0; e < 4; e++) { sm[e] = expf(noisy[e] - mx); ssum += sm[e]; }
#pragma unroll
    for (int e = 0; e < 4; e++) sm[e] /= ssum;
    int idx[4] = {0,1,2,3};
#pragma unroll
    for (int i = 0; i < 3; i++)
#pragma unroll
        for (int j = 0; j < 3; j++)
            if (j < 3 - i && sm[idx[j+1]] > sm[idx[j]]) { int t = idx[j]; idx[j] = idx[j+1]; idx[j+1] = t; }
    float v1 = sm[idx[1]], v2 = sm[idx[2]];
    float eb = expf(v1 - sm[idx[0]]);
    float g0 = 1.f / (1.f + eb), g1 = eb / (1.f + eb);
    float gr[4] = {0,0,0,0};
    gr[idx[0]] = g0; gr[idx[1]] = g1;
#pragma unroll
    for (int e = 0; e < 4; e++) { g_gates[b * 4 + e] = gr[e]; sh_g[b][e] = gr[e]; }
#pragma unroll
    for (int e = 0; e < 4; e++) {
        bool isin = noisy[e] > v2;
        float thr = isin ? v2 : v1;
        sh_p[b][e] = normcdff((clean[e] - thr) / sd[e]);
    }
    __syncthreads();
    if (b == 0) {
        float imp[4] = {0,0,0,0}, ld[4] = {0,0,0,0};
        for (int bb = 0; bb < BB; bb++)
#pragma unroll
            for (int e = 0; e < 4; e++) { imp[e] += sh_g[bb][e]; ld[e] += sh_p[bb][e]; }
        float m1 = (imp[0]+imp[1]+imp[2]+imp[3]) * 0.25f, va = 0.f;
#pragma unroll
        for (int e = 0; e < 4; e++) { float d = imp[e]-m1; va += d*d; }
        float cv1 = (va * (1.f/3.f)) / (m1*m1 + 1e-10f);
        float m2 = (ld[0]+ld[1]+ld[2]+ld[3]) * 0.25f, vb = 0.f;
#pragma unroll
        for (int e = 0; e < 4; e++) { float d = ld[e]-m2; vb += d*d; }
        float cv2 = (vb * (1.f/3.f)) / (m2*m2 + 1e-10f);
        loss_out[0] = 0.01f * (cv1 + cv2);
    }
}

// ---------------- kernel 3: fused experts (TF32 mma, TL=64, 512 threads) ----------------
__global__ void __launch_bounds__(NT, 1)
expert_kernel(const float* __restrict__ x, const float* __restrict__ b1,
              const float* __restrict__ b2, const float* __restrict__ b3,
              const float* __restrict__ bp, float* __restrict__ y) {
    extern __shared__ float smf[];
    float* xs = smf;
    float* h1 = smf + H1_OFF;
    float* h2 = smf + H2_OFF;
    float* ws = smf + WS_OFF;
    const int tid = threadIdx.x;
    const int b = blockIdx.y;
    const int l0 = blockIdx.x * TL;
    const int w = tid >> 5, lane = tid & 31;
    const int gid = lane >> 2, tig = lane & 3;

    // load x tile + halo, pre-truncated to TF32
    {
        const float* xb = x + (size_t)b * CC * LL + l0;
        for (int i = tid; i < CC * 16; i += NT) {
            int c = i >> 4, j = i & 15;
            float4 v = *(const float4*)(xb + (size_t)c * LL + j * 4);
            v.x = tf32f(v.x); v.y = tf32f(v.y); v.z = tf32f(v.z); v.w = tf32f(v.w);
            *(float4*)&xs[c * XS_STRIDE + 4 + j * 4] = v;
        }
        for (int i = tid; i < 2 * CC; i += NT) {
            int side = i >> 8, c = i & 255;
            int l = side ? (l0 + TL) : (l0 - 1);
            float v = 0.f;
            if (l >= 0 && l < LL) v = tf32f(xb[(size_t)c * LL + (side ? TL : -1)]);
            xs[c * XS_STRIDE + (side ? 68 : 3)] = v;
        }
    }
    __syncthreads();

    bool wrote = false;
    for (int e = 0; e < EE; e++) {
        float gv = g_gates[b * 4 + e];
        if (gv == 0.f) continue;

        // ---- stage 1: h1 = relu(W1@x + b1), 16 warps: 4m x 4n of 16x16 ----
        {
            const int nbase = (w >> 2) * 16;
            const int r0 = (w & 3) * 16 + gid;
            float cf[2][4];
            float bias0 = b1[e*BN + r0], bias1 = b1[e*BN + r0 + 8];
#pragma unroll
            for (int nt = 0; nt < 2; nt++) {
                cf[nt][0] = bias0; cf[nt][1] = bias0;
                cf[nt][2] = bias1; cf[nt][3] = bias1;
            }
            const int hside = tid >> 6, hm = tid & 63;
            const int hp = (hside | (tid >> 7)) ? 68 : 3;
            const int hl = hside ? (l0 + TL) : (l0 - 1);
            const bool hvalid = (tid < 128) && (hl >= 0) && (hl < LL);
            float hacc = (tid < 128) ? b1[e * BN + hm] : 0.f;
            const float* w1t = g_wt + W1T + (size_t)e * BN * CC;
#pragma unroll
            for (int t = 0; t < 2; t++) {
                int i = tid + t * NT, kg = i & 15, m = i >> 4;
                cpa16(&ws[m*68 + kg*4], w1t + m*CC + kg*4);
            }
            CP_COMMIT(); CP_WAIT0();
            __syncthreads();
            for (int c = 0; c < 4; c++) {
                if (c < 3) {
                    float* nb = ws + ((c+1) & 1) * S1P;
#pragma unroll
                    for (int t = 0; t < 2; t++) {
                        int i = tid + t * NT, kg = i & 15, m = i >> 4;
                        cpa16(&nb[m*68 + kg*4], w1t + m*CC + (c+1)*64 + kg*4);
                    }
                    CP_COMMIT();
                }
                const float* wb = ws + (c & 1) * S1P;
                const float* rA0 = wb + r0 * 68;
                const float* rA1 = wb + (r0 + 8) * 68;
#pragma unroll
                for (int ks = 0; ks < 8; ks++) {
                    unsigned af[4];
                    af[0] = __float_as_uint(rA0[8*ks + tig]);
                    af[1] = __float_as_uint(rA1[8*ks + tig]);
                    af[2] = __float_as_uint(rA0[8*ks + tig + 4]);
                    af[3] = __float_as_uint(rA1[8*ks + tig + 4]);
                    const float* rB0 = &xs[(c*64 + 8*ks + tig) * XS_STRIDE + 4 + nbase];
                    const float* rB1 = rB0 + 4 * XS_STRIDE;
#pragma unroll
                    for (int nt = 0; nt < 2; nt++) {
                        unsigned bf[2] = {__float_as_uint(rB0[nt*8 + gid]),
                                          __float_as_uint(rB1[nt*8 + gid])};
                        mma_tf32(cf[nt], af, bf);
                    }
                }
                if (tid < 128) {
                    const float* hrow = wb + hm * 68;
#pragma unroll 4
                    for (int k4 = 0; k4 < 16; k4++) {
                        float4 wv = *(const float4*)&hrow[k4*4];
                        const float* xp = &xs[(c*64 + k4*4)*XS_STRIDE + hp];
                        hacc = fmaf(wv.x, xp[0], hacc);
                        hacc = fmaf(wv.y, xp[XS_STRIDE], hacc);
                        hacc = fmaf(wv.z, xp[2*XS_STRIDE], hacc);
                        hacc = fmaf(wv.w, xp[3*XS_STRIDE], hacc);
                    }
                }
                CP_WAIT0();
                __syncthreads();
            }
#pragma unroll
            for (int nt = 0; nt < 2; nt++) {
                int col = 4 + nbase + nt*8 + 2*tig;
                float2 v0 = {tf32f(fmaxf(cf[nt][0],0.f)), tf32f(fmaxf(cf[nt][1],0.f))};
                float2 v1 = {tf32f(fmaxf(cf[nt][2],0.f)), tf32f(fmaxf(cf[nt][3],0.f))};
                *(float2*)&h1[r0*XS_STRIDE + col] = v0;
                *(float2*)&h1[(r0+8)*XS_STRIDE + col] = v1;
            }
            if (tid < 128) h1[hm * XS_STRIDE + hp] = hvalid ? tf32f(fmaxf(hacc, 0.f)) : 0.f;
        }

        // ---- stage 2: h2 = relu(conv3(h1) + b2), weights [d][m][68] ----
        {
            const int nbase = (w >> 2) * 16;
            const int r0 = (w & 3) * 16 + gid;
            const float* w2t = g_wt + W2T + (size_t)e * 3 * BN * 64;
#pragma unroll
            for (int t = 0; t < 6; t++) {
                int i = tid + t * NT, kg = i & 15, dm = i >> 4;
                int m = dm & 63, d = dm >> 6;
                cpa16(&ws[d*S1P + m*68 + kg*4], w2t + (d*BN + m)*64 + kg*4);
            }
            CP_COMMIT();
            float cf[2][4];
            float bias0 = b2[e*BN + r0], bias1 = b2[e*BN + r0 + 8];
#pragma unroll
            for (int nt = 0; nt < 2; nt++) {
                cf[nt][0] = bias0; cf[nt][1] = bias0;
                cf[nt][2] = bias1; cf[nt][3] = bias1;
            }
            CP_WAIT0();
            __syncthreads();   // weights ready + h1 visible
#pragma unroll
            for (int d = 0; d < 3; d++) {
                const float* wd = ws + d * S1P;
                const float* rA0 = wd + r0 * 68;
                const float* rA1 = wd + (r0 + 8) * 68;
#pragma unroll
                for (int ks = 0; ks < 8; ks++) {
                    unsigned af[4];
                    af[0] = __float_as_uint(rA0[8*ks + tig]);
                    af[1] = __float_as_uint(rA1[8*ks + tig]);
                    af[2] = __float_as_uint(rA0[8*ks + tig + 4]);
                    af[3] = __float_as_uint(rA1[8*ks + tig + 4]);
                    const float* rB0 = &h1[(8*ks + tig) * XS_STRIDE + 3 + d + nbase];
                    const float* rB1 = rB0 + 4 * XS_STRIDE;
#pragma unroll
                    for (int nt = 0; nt < 2; nt++) {
                        unsigned bf[2] = {__float_as_uint(rB0[nt*8 + gid]),
                                          __float_as_uint(rB1[nt*8 + gid])};
                        mma_tf32(cf[nt], af, bf);
                    }
                }
            }
            __syncthreads();   // ws reads done before stage-3 cp
#pragma unroll
            for (int nt = 0; nt < 2; nt++) {
                int col = 4 + nbase + nt*8 + 2*tig;
                float2 v0 = {tf32f(fmaxf(cf[nt][0],0.f)), tf32f(fmaxf(cf[nt][1],0.f))};
                float2 v1 = {tf32f(fmaxf(cf[nt][2],0.f)), tf32f(fmaxf(cf[nt][3],0.f))};
                *(float2*)&h2[r0*XS_STRIDE + col] = v0;
                *(float2*)&h2[(r0+8)*XS_STRIDE + col] = v1;
            }
        }

        // ---- stage 3: y += g*relu(Wp@x + W3@h2 + bp + b3), 16 warps x 16 rows ----
        {
            const int m0w = w * 16;
            const int r0 = m0w + gid;
            const float* wpt = g_wt + WPT + (size_t)e * CC * CC;
            const float* w3t = g_wt + W3T + (size_t)e * CC * BN;
            float cf[8][4];
            float bias0 = bp[e*CC + r0] + b3[e*CC + r0];
            float bias1 = bp[e*CC + r0 + 8] + b3[e*CC + r0 + 8];
#pragma unroll
            for (int nt = 0; nt < 8; nt++) {
                cf[nt][0] = bias0; cf[nt][1] = bias0;
                cf[nt][2] = bias1; cf[nt][3] = bias1;
            }
            // prologue: cp chunk 0 (wp k=0..31), [m][36]
#pragma unroll
            for (int t = 0; t < 4; t++) {
                int i = tid + t * NT, kg = i & 7, m = i >> 3;
                cpa16(&ws[m*36 + kg*4], wpt + m*CC + kg*4);
            }
            CP_COMMIT(); CP_WAIT0();
            __syncthreads();   // chunk0 ready + h2 visible
            for (int ch = 0; ch < 10; ch++) {
                if (ch < 9) {
                    int nc = ch + 1;
                    float* nb = ws + (nc & 1) * S3P;
#pragma unroll
                    for (int t = 0; t < 4; t++) {
                        int i = tid + t * NT, kg = i & 7, m = i >> 3;
                        const float* src = (nc < 8) ? (wpt + m*CC + nc*32 + kg*4)
                                                    : (w3t + m*BN + (nc-8)*32 + kg*4);
                        cpa16(&nb[m*36 + kg*4], src);
                    }
                    CP_COMMIT();
                }
                const float* wb = ws + (ch & 1) * S3P;
                const float* opb = (ch < 8) ? &xs[(ch*32)*XS_STRIDE + 4]
                                            : &h2[((ch-8)*32)*XS_STRIDE + 4];
                const float* rA0 = wb + r0 * 36;
                const float* rA1 = rA0 + 8 * 36;
#pragma unroll
                for (int ks = 0; ks < 4; ks++) {
                    unsigned af[4];
                    af[0] = __float_as_uint(rA0[8*ks + tig]);
                    af[1] = __float_as_uint(rA1[8*ks + tig]);
                    af[2] = __float_as_uint(rA0[8*ks + tig + 4]);
                    af[3] = __float_as_uint(rA1[8*ks + tig + 4]);
                    const float* rowB0 = opb + (8*ks + tig) * XS_STRIDE;
                    const float* rowB1 = opb + (8*ks + tig + 4) * XS_STRIDE;
#pragma unroll
                    for (int nt = 0; nt < 8; nt++) {
                        unsigned bf[2] = {__float_as_uint(rowB0[nt*8 + gid]),
                                          __float_as_uint(rowB1[nt*8 + gid])};
                        mma_tf32(cf[nt], af, bf);
                    }
                }
                CP_WAIT0();
                __syncthreads();
            }
#pragma unroll
            for (int nt = 0; nt < 8; nt++) {
                float* yp0 = y + ((size_t)b*CC + r0)*LL + l0 + nt*8 + 2*tig;
                float* yp1 = yp0 + (size_t)8*LL;
                float2 v0 = {fmaxf(cf[nt][0],0.f)*gv, fmaxf(cf[nt][1],0.f)*gv};
                float2 v1 = {fmaxf(cf[nt][2],0.f)*gv, fmaxf(cf[nt][3],0.f)*gv};
                if (wrote) {
                    float2 o0 = *(float2*)yp0, o1 = *(float2*)yp1;
                    v0.x += o0.x; v0.y += o0.y; v1.x += o1.x; v1.y += o1.y;
                }
                *(float2*)yp0 = v0; *(float2*)yp1 = v1;
            }
        }
        wrote = true;
    }
}

extern "C" void kernel_launch(void* const* d_in, const int* in_sizes, int n_in,
                              void* d_out, int out_size) {
    const float* x     = (const float*)d_in[0];
    const float* noise = (const float*)d_in[1];
    const float* wg    = (const float*)d_in[2];
    const float* wn    = (const float*)d_in[3];
    const float* W1    = (const float*)d_in[4];
    const float* b1    = (const float*)d_in[5];
    const float* W2    = (const float*)d_in[6];
    const float* b2    = (const float*)d_in[7];
    const float* W3    = (const float*)d_in[8];
    const float* b3    = (const float*)d_in[9];
    const float* Wp    = (const float*)d_in[10];
    const float* bp    = (const float*)d_in[11];
    float* y = (float*)d_out;
    float* loss = y + (size_t)out_size - 1;

    cudaFuncSetAttribute(expert_kernel, cudaFuncAttributeMaxDynamicSharedMemorySize, SMEM_BYTES);

    prep_kernel<<<(WT_TOTAL + 255) / 256, 256>>>(W1, W2, W3, Wp);  // also keeps ncu window
    mean_kernel<<<BB * CC, 256>>>(x);
    gating_kernel<<<1, BB>>>(noise, wg, wn, loss);
    dim3 grid(LL / TL, BB);
    expert_kernel<<<grid, NT, SMEM_BYTES>>>(x, b1, b2, b3, bp, y);
}